// round 15
// baseline (speedup 1.0000x reference)
#include <cuda_runtime.h>
#include <cstddef>

#define BDIM 1024
#define SDIM 258
#define IDIM 512
#define HDIM 512
#define G4   (4*HDIM)   // 2048

#define BM 128
#define BN 64
#define BK 16
#define TM 8
#define TN 4

// ---------------- scratch (device globals; no allocations allowed) ----------
__device__ __align__(16) float g_gates_r[(size_t)BDIM*G4];
__device__ __align__(16) float g_gates_l[(size_t)BDIM*G4];
__device__ __align__(16) float g_hlcat[(size_t)BDIM*(2*HDIM)];     // [h_r | h_l]
__device__ __align__(16) float g_hr[(size_t)BDIM*HDIM];
__device__ __align__(16) float g_cr[(size_t)BDIM*HDIM];

__device__ __forceinline__ float sigf(float x) { return 1.0f / (1.0f + expf(-x)); }

// ------- branch-free, software-pipelined segment copy (float4 units) --------
// Copies s[i0..i1) -> d[i0..i1), block-interleaved across ncpy copy blocks.
// Double-buffered batches of 4: next batch's loads issue before current
// batch's stores, keeping ~8 LDG.128 outstanding per thread continuously.
__device__ __forceinline__ void copy_seg(
    const float4* __restrict__ s, float4* __restrict__ d,
    size_t i0, size_t i1, int cb, int ncpy)
{
    const size_t stride = (size_t)ncpy * 256;
    size_t i = i0 + (size_t)cb * 256 + threadIdx.x;

    if (i + 3 * stride < i1) {
        float4 a0 = s[i];
        float4 a1 = s[i + stride];
        float4 a2 = s[i + 2 * stride];
        float4 a3 = s[i + 3 * stride];
        size_t inext = i + 4 * stride;
        while (inext + 3 * stride < i1) {
            float4 b0 = s[inext];
            float4 b1 = s[inext + stride];
            float4 b2 = s[inext + 2 * stride];
            float4 b3 = s[inext + 3 * stride];
            d[i] = a0;
            d[i + stride] = a1;
            d[i + 2 * stride] = a2;
            d[i + 3 * stride] = a3;
            a0 = b0; a1 = b1; a2 = b2; a3 = b3;
            i = inext;
            inext += 4 * stride;
        }
        d[i] = a0;
        d[i + stride] = a1;
        d[i + 2 * stride] = a2;
        d[i + 3 * stride] = a3;
        i = inext;
    }
    for (; i < i1; i += stride) d[i] = s[i];
}

// Copy role over unified unit space [c0, c1) in [0, 2*n4): h first, then c.
__device__ __forceinline__ void copy_role(
    int cb, int ncpy, size_t c0, size_t c1, size_t n4,
    const float4* __restrict__ csh, const float4* __restrict__ csc,
    float4* __restrict__ cdh, float4* __restrict__ cdc)
{
    if (c0 < n4) {
        size_t e = (c1 < n4) ? c1 : n4;
        copy_seg(csh, cdh, c0, e, cb, ncpy);
    }
    if (c1 > n4) {
        size_t b = (c0 > n4) ? (c0 - n4) : 0;
        copy_seg(csc, cdc, b, c1 - n4, cb, ncpy);
    }
}

// ---------------- GEMM tile: C[bm:bm+128, bn:bn+64] = A @ W^T + b (+tanh) ---
// a_mode 0: A0 row-major (M,K).  a_mode 1: A = [char | sh[b, pos[b]]] gather.
// W(n,k) = k<K1 ? W1 : W2.
__device__ __forceinline__ void gemm_tile(
    int block_m, int block_n, int a_mode,
    const float* __restrict__ A0,
    const float* __restrict__ sh, const int* __restrict__ pos,
    const float* __restrict__ W1, const float* __restrict__ W2,
    int K1, int K,
    const float* __restrict__ b1, const float* __restrict__ b2,
    float* __restrict__ C, int N, int act,
    float (*As)[BM], float (*Bs)[BN], int* pos_s)
{
    int tid = threadIdx.x;
    int tx = tid & 15;
    int ty = tid >> 4;

    if (a_mode == 1 && tid < BM) pos_s[tid] = pos[block_m + tid];
    __syncthreads();

    float acc[TM][TN];
    #pragma unroll
    for (int i = 0; i < TM; i++)
        #pragma unroll
        for (int j = 0; j < TN; j++) acc[i][j] = 0.0f;

    for (int k0 = 0; k0 < K; k0 += BK) {
        #pragma unroll
        for (int it = 0; it < 2; it++) {
            int li = tid + it * 256;
            int m  = li >> 2;
            int kq = (li & 3) << 2;
            int mg = block_m + m;
            int kk = k0 + kq;
            const float* src;
            if (a_mode == 0) {
                src = &A0[(size_t)mg * K + kk];
            } else if (kk < IDIM) {
                src = &A0[(size_t)mg * IDIM + kk];
            } else {
                src = &sh[((size_t)mg * SDIM + pos_s[m]) * HDIM + (kk - IDIM)];
            }
            float4 v = *reinterpret_cast<const float4*>(src);
            As[kq + 0][m] = v.x; As[kq + 1][m] = v.y;
            As[kq + 2][m] = v.z; As[kq + 3][m] = v.w;
        }
        {
            int li = tid;
            int n  = li >> 2;
            int kq = (li & 3) << 2;
            int kk = k0 + kq;
            const float* Wp; int kw, Kw;
            if (kk < K1) { Wp = W1; kw = kk;       Kw = K1;     }
            else         { Wp = W2; kw = kk - K1;  Kw = K - K1; }
            float4 v = *reinterpret_cast<const float4*>(
                &Wp[(size_t)(block_n + n) * Kw + kw]);
            Bs[kq + 0][n] = v.x; Bs[kq + 1][n] = v.y;
            Bs[kq + 2][n] = v.z; Bs[kq + 3][n] = v.w;
        }
        __syncthreads();

        #pragma unroll
        for (int kk = 0; kk < BK; kk++) {
            float4 a0 = *reinterpret_cast<const float4*>(&As[kk][ty * TM]);
            float4 a1 = *reinterpret_cast<const float4*>(&As[kk][ty * TM + 4]);
            float4 bv = *reinterpret_cast<const float4*>(&Bs[kk][tx * TN]);
            float a[TM] = {a0.x, a0.y, a0.z, a0.w, a1.x, a1.y, a1.z, a1.w};
            float bcol[TN] = {bv.x, bv.y, bv.z, bv.w};
            #pragma unroll
            for (int i = 0; i < TM; i++)
                #pragma unroll
                for (int j = 0; j < TN; j++)
                    acc[i][j] += a[i] * bcol[j];
        }
        __syncthreads();
    }

    float bb[TN];
    #pragma unroll
    for (int j = 0; j < TN; j++) {
        int n = block_n + tx * TN + j;
        float bsum = b1[n];
        if (b2) bsum += b2[n];
        bb[j] = bsum;
    }
    #pragma unroll
    for (int i = 0; i < TM; i++) {
        int m = block_m + ty * TM + i;
        float r[TN];
        #pragma unroll
        for (int j = 0; j < TN; j++) {
            float x = acc[i][j] + bb[j];
            if (act == 1) x = tanhf(x);
            r[j] = x;
        }
        *reinterpret_cast<float4*>(&C[(size_t)m * N + block_n + tx * TN]) =
            make_float4(r[0], r[1], r[2], r[3]);
    }
}

#define NCPY1 148
#define NCPY2 340
#define NCPY3 380

// ================= L1: copy slice 1 + all 512 gates tiles ===================
__global__ void __launch_bounds__(256, 3)
mega1_kernel(const float* __restrict__ ch,
             const float* __restrict__ sh,
             const float* __restrict__ sc,
             const int* __restrict__ pos,
             const float* __restrict__ W_ih_r, const float* __restrict__ W_hh_r,
             const float* __restrict__ b_ih_r, const float* __restrict__ b_hh_r,
             const float* __restrict__ W_ih_l,
             const float* __restrict__ b_ih_l, const float* __restrict__ b_hh_l,
             float4* __restrict__ cdh, float4* __restrict__ cdc,
             size_t n4, size_t c0, size_t c1)
{
    __shared__ __align__(16) float As[BK][BM];
    __shared__ __align__(16) float Bs[BK][BN];
    __shared__ int pos_s[BM];

    int bid = blockIdx.x;
    if (bid < NCPY1) {
        copy_role(bid, NCPY1, c0, c1, n4,
                  (const float4*)sh, (const float4*)sc, cdh, cdc);
        return;
    }
    int w = bid - NCPY1;   // 0..295
    for (int t = w; t < 512; t += 296) {
        if (t < 256) {
            // gemm_r: [char | h@pos] @ [W_ih_r ; W_hh_r]^T, K=1024
            int by = t >> 5, bx = t & 31;    // 8 x 32 tiles, N=2048
            gemm_tile(by * BM, bx * BN, 1, ch, sh, pos,
                      W_ih_r, W_hh_r, IDIM, IDIM + HDIM,
                      b_ih_r, b_hh_r, g_gates_r, G4, 0, As, Bs, pos_s);
        } else {
            // gemm_l: char @ W_ih_l^T, K=512
            int tl = t - 256;
            int by = tl >> 5, bx = tl & 31;
            gemm_tile(by * BM, bx * BN, 0, ch, nullptr, nullptr,
                      W_ih_l, nullptr, IDIM, IDIM,
                      b_ih_l, b_hh_l, g_gates_l, G4, 0, As, Bs, pos_s);
        }
    }
}

// ================= L2: copy slice 2 + LSTM elementwise ======================
__global__ void __launch_bounds__(256, 3)
mega2_kernel(const float* __restrict__ sh,
             const float* __restrict__ sc,
             const int* __restrict__ pos,
             float4* __restrict__ cdh, float4* __restrict__ cdc,
             size_t n4, size_t c0, size_t c1)
{
    int bid = blockIdx.x;
    if (bid < NCPY2) {
        copy_role(bid, NCPY2, c0, c1, n4,
                  (const float4*)sh, (const float4*)sc, cdh, cdc);
        return;
    }
    int nwork = gridDim.x - NCPY2;
    int stride = nwork * 256;
    for (int idx = (bid - NCPY2) * 256 + threadIdx.x; idx < BDIM * HDIM;
         idx += stride) {
        int b = idx / HDIM;
        int j = idx - b * HDIM;

        const float* gr = g_gates_r + (size_t)b * G4;
        const float* gl = g_gates_l + (size_t)b * G4;

        float ig = gr[j];
        float fg = gr[HDIM + j];
        float gg = gr[2 * HDIM + j];
        float og = gr[3 * HDIM + j];

        int p = pos[b];
        float cprev = sc[((size_t)b * SDIM + p) * HDIM + j];
        float cr = sigf(fg) * cprev + sigf(ig) * tanhf(gg);
        float hr = sigf(og) * tanhf(cr);

        float cl = sigf(gl[j]) * tanhf(gl[2 * HDIM + j]);
        float hl = sigf(gl[3 * HDIM + j]) * tanhf(cl);

        g_hlcat[(size_t)b * (2 * HDIM) + j]        = hr;
        g_hlcat[(size_t)b * (2 * HDIM) + HDIM + j] = hl;
        g_hr[idx] = hr;
        g_cr[idx] = cr;
    }
}

// ================= L3: copy slice 3 + compose tiles =========================
__global__ void __launch_bounds__(256, 3)
mega3_kernel(const float* __restrict__ sh,
             const float* __restrict__ sc,
             const float* __restrict__ W_comp, const float* __restrict__ b_comp,
             float* __restrict__ out_sub,
             float4* __restrict__ cdh, float4* __restrict__ cdc,
             size_t n4, size_t c0, size_t c1)
{
    __shared__ __align__(16) float As[BK][BM];
    __shared__ __align__(16) float Bs[BK][BN];
    __shared__ int pos_s[BM];

    int bid = blockIdx.x;
    if (bid < NCPY3) {
        copy_role(bid, NCPY3, c0, c1, n4,
                  (const float4*)sh, (const float4*)sc, cdh, cdc);
        return;
    }
    int t = bid - NCPY3;   // 0..63: 8 m-tiles x 8 n-tiles, N=512
    int by = t >> 3, bx = t & 7;
    gemm_tile(by * BM, bx * BN, 0, g_hlcat, nullptr, nullptr,
              W_comp, nullptr, 2 * HDIM, 2 * HDIM,
              b_comp, nullptr, out_sub, HDIM, 1, As, Bs, pos_s);
}

// ================= L4: scatter h_r/c_r at pos+1 =============================
__global__ void scatter_kernel(const int* __restrict__ pos,
                               float4* __restrict__ out_h,
                               float4* __restrict__ out_c) {
    int idx = blockIdx.x * blockDim.x + threadIdx.x;   // over B*H/4
    if (idx >= BDIM * (HDIM / 4)) return;
    int b = idx / (HDIM / 4);
    int q = idx - b * (HDIM / 4);
    const float4* hr = (const float4*)g_hr;
    const float4* cr = (const float4*)g_cr;
    int p = pos[b] + 1;
    size_t off = ((size_t)b * SDIM + p) * (HDIM / 4) + q;
    out_h[off] = hr[(size_t)b * (HDIM / 4) + q];
    out_c[off] = cr[(size_t)b * (HDIM / 4) + q];
}

// ---------------------------------------------------------------------------
extern "C" void kernel_launch(void* const* d_in, const int* in_sizes, int n_in,
                              void* d_out, int out_size) {
    const float* ch     = (const float*)d_in[0];
    const float* sh     = (const float*)d_in[1];
    const float* sc     = (const float*)d_in[2];
    const int*   pos    = (const int*)d_in[3];
    const float* W_ih_r = (const float*)d_in[4];
    const float* W_hh_r = (const float*)d_in[5];
    const float* b_ih_r = (const float*)d_in[6];
    const float* b_hh_r = (const float*)d_in[7];
    const float* W_ih_l = (const float*)d_in[8];
    const float* W_hh_l = (const float*)d_in[9];   (void)W_hh_l;  // h=0, unused
    const float* b_ih_l = (const float*)d_in[10];
    const float* b_hh_l = (const float*)d_in[11];
    const float* W_comp = (const float*)d_in[12];
    const float* b_comp = (const float*)d_in[13];

    float* out      = (float*)d_out;
    float* out_sub  = out;                                    // (B, H)
    float* out_h    = out + (size_t)BDIM * HDIM;              // (B, S, H)
    float* out_c    = out_h + (size_t)BDIM * SDIM * HDIM;     // (B, S, H)

    const size_t n4 = (size_t)BDIM * SDIM * HDIM / 4;   // 33,816,576
    const size_t U  = 2 * n4;                           // 67,633,152 units
    float4* cdh = (float4*)out_h;
    float4* cdc = (float4*)out_c;

    // slice boundaries: s1 sized so L1's copy (~18M units) hides under the
    // gates GEMMs; remainder split between L2 (copy-heavy) and L3.
    const size_t s1 = 18000000;
    const size_t s2 = s1 + 20000000;
    // L3 covers [s2, U) = ~29.6M units

    // L1: copy slice1 + gates_r (inline gather) + gates_l
    mega1_kernel<<<NCPY1 + 296, 256>>>(ch, sh, sc, pos,
                                       W_ih_r, W_hh_r, b_ih_r, b_hh_r,
                                       W_ih_l, b_ih_l, b_hh_l,
                                       cdh, cdc, n4, 0, s1);
    // L2: copy slice2 + LSTM elementwise
    mega2_kernel<<<NCPY2 + 104, 256>>>(sh, sc, pos, cdh, cdc, n4, s1, s2);
    // L3: copy slice3 + compose (tanh) -> out_sub
    mega3_kernel<<<NCPY3 + 64, 256>>>(sh, sc, W_comp, b_comp, out_sub,
                                      cdh, cdc, n4, s2, U);
    // L4: scatter (h_r, c_r) at pos+1
    {
        int total = BDIM * (HDIM / 4);
        scatter_kernel<<<(total + 255) / 256, 256>>>(pos, (float4*)out_h,
                                                     (float4*)out_c);
    }
}